// round 5
// baseline (speedup 1.0000x reference)
#include <cuda_runtime.h>
#include <cstdint>
#include <cstddef>

#define BB 256
#define TT 2048
#define DD0 57
#define HH 16
#define GG 64
#define NPOS (BB*TT)            // 524288
#define NGATE ((size_t)NPOS*GG) // 33554432

typedef unsigned long long u64;

// ---------------- scratch (device globals, no allocation) ----------------
__device__ float g_xg[NGATE];                    // gate preacts: [pos][half][unit][2]
__device__ float g_ha[(size_t)NPOS * HH];        // h ping
__device__ float g_hb[(size_t)NPOS * HH];        // h pong
__device__ float g_stats[32];                    // [0:16) sum, [16:32) sumsq
__device__ float g_coef[68];                     // [0:64) w'[o][j], [64:68) b'[o]

// ---------------- f32x2 packed helpers ------------------------------------
__device__ __forceinline__ u64 pk2(float lo, float hi) {
    u64 r; asm("mov.b64 %0,{%1,%2};" : "=l"(r) : "f"(lo), "f"(hi)); return r;
}
__device__ __forceinline__ void upk2(float& lo, float& hi, u64 v) {
    asm("mov.b64 {%0,%1},%2;" : "=f"(lo), "=f"(hi) : "l"(v));
}
__device__ __forceinline__ u64 fma2(u64 a, u64 b, u64 c) {
    u64 r; asm("fma.rn.f32x2 %0,%1,%2,%3;" : "=l"(r) : "l"(a), "l"(b), "l"(c)); return r;
}
__device__ __forceinline__ u64 add2(u64 a, u64 b) {
    u64 r; asm("add.rn.f32x2 %0,%1,%2;" : "=l"(r) : "l"(a), "l"(b)); return r;
}

// ---------------- fast activations (MUFU.TANH) ----------------------------
__device__ __forceinline__ float f_tanh(float x) {
    float r; asm("tanh.approx.f32 %0,%1;" : "=f"(r) : "f"(x)); return r;
}

// ---------------- input projection ---------------------------------------
// out layout: xg[pos*64 + ((r>>5)<<5) + ((r&15)<<1) + ((r>>4)&1)]
//   half0 (floats 0..31):  unit j -> (i_pre, f_pre) at (2j, 2j+1)
//   half1 (floats 32..63): unit j -> (g_pre, o_pre) at (32+2j, 32+2j+1)
template<int DIN, int PPB>
__global__ void __launch_bounds__(256)
proj_kernel(const float* __restrict__ in,
            const float* __restrict__ W,
            const float* __restrict__ bih,
            const float* __restrict__ bhh,
            float* __restrict__ xg)
{
    constexpr int DPAD = (DIN % 2 == 0) ? (DIN + 1) : DIN;   // odd stride: conflict-free
    constexpr int XPAD = ((DIN + 3) / 4) * 4;                 // 16B-aligned x rows
    __shared__ __align__(16) float sx[PPB * XPAD];
    __shared__ float sw[64 * DPAD];

    const int tid = threadIdx.x;
    const int r   = tid & 63;
    const int posBase = blockIdx.x * PPB;

    for (int i = tid; i < PPB * DIN; i += 256)
        sx[(i / DIN) * XPAD + (i % DIN)] = in[(size_t)posBase * DIN + i];
    for (int i = tid; i < 64 * DIN; i += 256)
        sw[(i / DIN) * DPAD + (i % DIN)] = W[i];
    __syncthreads();

    float w[DIN];
#pragma unroll
    for (int d = 0; d < DIN; ++d) w[d] = sw[r * DPAD + d];
    const float bias = __ldg(bih + r) + __ldg(bhh + r);
    const int outIdx = ((r >> 5) << 5) | ((r & 15) << 1) | ((r >> 4) & 1);

    constexpr int D4 = DIN / 4;
    for (int p = (tid >> 6); p < PPB; p += 4) {
        const float* xp = &sx[p * XPAD];
        float acc = bias;
#pragma unroll
        for (int d4 = 0; d4 < D4; ++d4) {
            float4 v = ((const float4*)xp)[d4];
            acc = fmaf(v.x, w[d4 * 4 + 0], acc);
            acc = fmaf(v.y, w[d4 * 4 + 1], acc);
            acc = fmaf(v.z, w[d4 * 4 + 2], acc);
            acc = fmaf(v.w, w[d4 * 4 + 3], acc);
        }
#pragma unroll
        for (int d = 4 * D4; d < DIN; ++d)
            acc = fmaf(xp[d], w[d], acc);
        xg[((size_t)(posBase + p) << 6) + outIdx] = acc;
    }
}

// ---------------- recurrent scan ------------------------------------------
// 32 lanes per batch: half0 lane j computes gates (i,f) of unit j; half1
// lane computes (g,o). c,h live on half0. Uniform (branchless) activations.
__global__ void __launch_bounds__(32)
scan_kernel(const float2* __restrict__ xg,   // [pos][lane] float2
            const float*  __restrict__ Whh,  // [64,16]
            float*        __restrict__ hout, // [B,T,16]
            const int*    __restrict__ lengths,
            int apply_mask)
{
    const int lane = threadIdx.x;
    const int j    = lane & 15;
    const int half = lane >> 4;
    const int b    = blockIdx.x;
    const bool oddj = (j & 1);

    // weight rows: lo gate row, hi gate row (k-packed f32x2 pairs)
    const int rlo = half ? (32 + j) : j;          // g : i
    const int rhi = half ? (48 + j) : (16 + j);   // o : f
    u64 wlo[8], whi[8];
    {
        const float2* plo = (const float2*)(Whh + rlo * 16);
        const float2* phi = (const float2*)(Whh + rhi * 16);
#pragma unroll
        for (int m = 0; m < 8; ++m) {
            float2 a = __ldg(plo + m), bb = __ldg(phi + m);
            wlo[m] = pk2(a.x, a.y);
            whi[m] = pk2(bb.x, bb.y);
        }
    }
    const int len = apply_mask ? lengths[b] : TT;

    const float2* xp = xg   + (size_t)b * TT * 32 + lane;
    float*        hp = hout + (size_t)b * TT * 16 + j;

    // activation constants: lo gate is sigm on half0 (i), tanh on half1 (g);
    // hi gate is sigm on both halves (f / o).   sigm(x)=0.5*tanh(0.5x)+0.5
    const float s_lo = half ? 1.0f : 0.5f;
    const float m_lo = half ? 1.0f : 0.5f;
    const float c_lo = half ? 0.0f : 0.5f;

    float c = 0.0f, h = 0.0f;

    float2 buf[8];
#pragma unroll
    for (int u = 0; u < 8; ++u) buf[u] = xp[u * 32];

    for (int tb = 0; tb < TT; tb += 8) {
#pragma unroll
        for (int u = 0; u < 8; ++u) {
            const int t = tb + u;
            const float2 cur = buf[u];
            int tn = t + 8; if (tn > TT - 1) tn = TT - 1;
            buf[u] = xp[tn * 32];                      // prefetch depth 8

            // build packed h-pair (h_{2m}, h_{2m+1}); valid on half0 lanes
            float e  = __shfl_xor_sync(0xffffffffu, h, 1);
            float plo = oddj ? e : h;
            float phi = oddj ? h : e;
            double h2d = __hiloint2double(__float_as_int(phi), __float_as_int(plo));

            u64 al0 = 0ull, al1 = 0ull, ah0 = 0ull, ah1 = 0ull;
#pragma unroll
            for (int m = 0; m < 8; m += 2) {
                double d0 = __shfl_sync(0xffffffffu, h2d, (m << 1),       32);
                double d1 = __shfl_sync(0xffffffffu, h2d, ((m + 1) << 1), 32);
                u64 u0 = (u64)__double_as_longlong(d0);
                u64 u1 = (u64)__double_as_longlong(d1);
                al0 = fma2(u0, wlo[m],     al0);
                ah0 = fma2(u0, whi[m],     ah0);
                al1 = fma2(u1, wlo[m + 1], al1);
                ah1 = fma2(u1, whi[m + 1], ah1);
            }
            float llo, lhi, hlo, hhi;
            upk2(llo, lhi, add2(al0, al1));
            upk2(hlo, hhi, add2(ah0, ah1));
            float a_l = cur.x + (llo + lhi);           // i (h0) / g (h1)
            float a_h = cur.y + (hlo + hhi);           // f (h0) / o (h1)

            float g_l = fmaf(m_lo, f_tanh(s_lo * a_l), c_lo);
            float g_h = fmaf(0.5f, f_tanh(0.5f * a_h), 0.5f);

            // exchange (g_l,g_h) across halves: half0 gets (gg,go)
            u64 own = pk2(g_l, g_h);
            double od = __shfl_xor_sync(0xffffffffu, __longlong_as_double((long long)own), 16);
            float o_l, o_h;
            upk2(o_l, o_h, (u64)__double_as_longlong(od));

            // half0: c = gf*c + gi*gg ; h = go * tanh(c)   (half1 computes garbage)
            c = fmaf(g_h, c, g_l * o_l);
            float tc = f_tanh(c);
            h = o_h * tc;

            if (half == 0)
                hp[t * 16] = (t < len) ? h : 0.0f;
        }
    }
}

// ---------------- BN stats --------------------------------------------------
__global__ void zero_stats_kernel() {
    if (threadIdx.x < 32) g_stats[threadIdx.x] = 0.0f;
}

__global__ void stats_kernel(const float* __restrict__ h2)
{
    __shared__ float ss[16], sq[16];
    int tid = threadIdx.x;
    if (tid < 16) { ss[tid] = 0.0f; sq[tid] = 0.0f; }
    __syncthreads();
    int j = tid & 15;
    int rpb = blockDim.x >> 4;
    float s = 0.0f, s2 = 0.0f;
    for (int pos = blockIdx.x * rpb + (tid >> 4); pos < NPOS; pos += gridDim.x * rpb) {
        float v = h2[(size_t)pos * 16 + j];
        s += v; s2 += v * v;
    }
    atomicAdd(&ss[j], s);
    atomicAdd(&sq[j], s2);
    __syncthreads();
    if (tid < 16) {
        atomicAdd(&g_stats[tid],      ss[tid]);
        atomicAdd(&g_stats[16 + tid], sq[tid]);
    }
}

// ---------------- fold BN into FC ------------------------------------------
__global__ void coef_kernel(const float* __restrict__ gamma,
                            const float* __restrict__ beta,
                            const float* __restrict__ fcw,
                            const float* __restrict__ fcb)
{
    __shared__ float scl[16], sht[16];
    int tid = threadIdx.x;
    if (tid < 16) {
        const float inv_n = 1.0f / (float)NPOS;
        float mean = g_stats[tid] * inv_n;
        float var  = g_stats[16 + tid] * inv_n - mean * mean;
        float s = rsqrtf(var + 1e-5f) * gamma[tid];
        scl[tid] = s;
        sht[tid] = beta[tid] - mean * s;
    }
    __syncthreads();
    if (tid < 64) {
        int o = tid >> 4, jj = tid & 15;
        g_coef[tid] = fcw[o * 16 + jj] * scl[jj];
    }
    if (tid < 4) {
        float bb = fcb[tid];
        for (int jj = 0; jj < 16; ++jj)
            bb += fcw[tid * 16 + jj] * sht[jj];
        g_coef[64 + tid] = bb;
    }
}

// ---------------- final GEMV ------------------------------------------------
__global__ void out_kernel(const float* __restrict__ h2, float* __restrict__ out)
{
    int pos = blockIdx.x * blockDim.x + threadIdx.x;
    if (pos >= NPOS) return;
    const float4* hp = (const float4*)(h2 + (size_t)pos * 16);
    float4 v0 = hp[0], v1 = hp[1], v2 = hp[2], v3 = hp[3];
    float hv[16] = { v0.x, v0.y, v0.z, v0.w, v1.x, v1.y, v1.z, v1.w,
                     v2.x, v2.y, v2.z, v2.w, v3.x, v3.y, v3.z, v3.w };
    float o0 = g_coef[64], o1 = g_coef[65], o2 = g_coef[66], o3 = g_coef[67];
#pragma unroll
    for (int jj = 0; jj < 16; ++jj) {
        float hvv = hv[jj];
        o0 = fmaf(hvv, g_coef[ 0 + jj], o0);
        o1 = fmaf(hvv, g_coef[16 + jj], o1);
        o2 = fmaf(hvv, g_coef[32 + jj], o2);
        o3 = fmaf(hvv, g_coef[48 + jj], o3);
    }
    float4 r = { o0, o1, o2, o3 };
    ((float4*)out)[pos] = r;
}

// ---------------- host ------------------------------------------------------
extern "C" void kernel_launch(void* const* d_in, const int* in_sizes, int n_in,
                              void* d_out, int out_size)
{
    const float* x    = (const float*)d_in[0];
    const int*   len  = (const int*)  d_in[1];
    const float* Wih0 = (const float*)d_in[2];
    const float* Whh0 = (const float*)d_in[3];
    const float* bih0 = (const float*)d_in[4];
    const float* bhh0 = (const float*)d_in[5];
    const float* Wih1 = (const float*)d_in[6];
    const float* Whh1 = (const float*)d_in[7];
    const float* bih1 = (const float*)d_in[8];
    const float* bhh1 = (const float*)d_in[9];
    const float* Wih2 = (const float*)d_in[10];
    const float* Whh2 = (const float*)d_in[11];
    const float* bih2 = (const float*)d_in[12];
    const float* bhh2 = (const float*)d_in[13];
    const float* gam  = (const float*)d_in[14];
    const float* bet  = (const float*)d_in[15];
    const float* fcw  = (const float*)d_in[16];
    const float* fcb  = (const float*)d_in[17];

    float *xg, *ha, *hb;
    cudaGetSymbolAddress((void**)&xg, g_xg);
    cudaGetSymbolAddress((void**)&ha, g_ha);
    cudaGetSymbolAddress((void**)&hb, g_hb);

    constexpr int PPB = 64;
    const int proj_grid = NPOS / PPB;   // 8192

    // layer 0
    proj_kernel<DD0, PPB><<<proj_grid, 256>>>(x, Wih0, bih0, bhh0, xg);
    scan_kernel<<<BB, 32>>>((const float2*)xg, Whh0, ha, len, 0);
    // layer 1
    proj_kernel<HH, PPB><<<proj_grid, 256>>>(ha, Wih1, bih1, bhh1, xg);
    scan_kernel<<<BB, 32>>>((const float2*)xg, Whh1, hb, len, 0);
    // layer 2 (mask applied at store)
    proj_kernel<HH, PPB><<<proj_grid, 256>>>(hb, Wih2, bih2, bhh2, xg);
    scan_kernel<<<BB, 32>>>((const float2*)xg, Whh2, ha, len, 1);

    // BN stats + fold into FC + output
    zero_stats_kernel<<<1, 32>>>();
    stats_kernel<<<1024, 256>>>(ha);
    coef_kernel<<<1, 64>>>(gam, bet, fcw, fcb);
    out_kernel<<<NPOS / 256, 256>>>(ha, (float*)d_out);
}

// round 6
// speedup vs baseline: 1.4387x; 1.4387x over previous
#include <cuda_runtime.h>
#include <cstdint>
#include <cstddef>

#define BB 256
#define TT 2048
#define DD0 57
#define HH 16
#define GG 64
#define NPOS (BB*TT)            // 524288
#define NGATE ((size_t)NPOS*GG) // 33554432

typedef unsigned long long u64;

// ---------------- scratch (device globals, no allocation) ----------------
__device__ float g_xg[NGATE + 512];              // gate preacts [pos][unit][4] + 8-step pad
__device__ float g_ha[(size_t)NPOS * HH];        // h ping
__device__ float g_hb[(size_t)NPOS * HH];        // h pong
__device__ float g_stats[32];                    // [0:16) sum, [16:32) sumsq
__device__ float g_coef[68];                     // [0:64) w'[o][j], [64:68) b'[o]

// ---------------- f32x2 packed helpers ------------------------------------
__device__ __forceinline__ u64 pk2(float lo, float hi) {
    u64 r; asm("mov.b64 %0,{%1,%2};" : "=l"(r) : "f"(lo), "f"(hi)); return r;
}
__device__ __forceinline__ void upk2(float& lo, float& hi, u64 v) {
    asm("mov.b64 {%0,%1},%2;" : "=f"(lo), "=f"(hi) : "l"(v));
}
__device__ __forceinline__ u64 fma2(u64 a, u64 b, u64 c) {
    u64 r; asm("fma.rn.f32x2 %0,%1,%2,%3;" : "=l"(r) : "l"(a), "l"(b), "l"(c)); return r;
}
__device__ __forceinline__ u64 add2(u64 a, u64 b) {
    u64 r; asm("add.rn.f32x2 %0,%1,%2;" : "=l"(r) : "l"(a), "l"(b)); return r;
}

// ---------------- fast activations (MUFU.TANH) ----------------------------
__device__ __forceinline__ float f_tanh(float x) {
    float r; asm("tanh.approx.f32 %0,%1;" : "=f"(r) : "f"(x)); return r;
}
__device__ __forceinline__ float f_sigm(float x) {
    float t = f_tanh(0.5f * x);
    return fmaf(0.5f, t, 0.5f);
}

// ---------------- input projection (f32x2 inner loop) ---------------------
// out layout: xg[pos*64 + (r&15)*4 + (r>>4)]  (per-unit float4 = i,f,g,o)
template<int DIN, int PPB>
__global__ void __launch_bounds__(256)
proj_kernel(const float* __restrict__ in,
            const float* __restrict__ W,
            const float* __restrict__ bih,
            const float* __restrict__ bhh,
            float* __restrict__ xg)
{
    constexpr int DPAD = (DIN % 2 == 0) ? (DIN + 1) : DIN;   // odd stride for sw
    constexpr int XPAD = ((DIN + 3) / 4) * 4;                 // 16B-aligned x rows
    __shared__ __align__(16) float sx[PPB * XPAD];
    __shared__ float sw[64 * DPAD];

    const int tid = threadIdx.x;
    const int r   = tid & 63;
    const int posBase = blockIdx.x * PPB;

    for (int i = tid; i < PPB * DIN; i += 256)
        sx[(i / DIN) * XPAD + (i % DIN)] = in[(size_t)posBase * DIN + i];
    for (int i = tid; i < 64 * DIN; i += 256)
        sw[(i / DIN) * DPAD + (i % DIN)] = W[i];
    __syncthreads();

    constexpr int NP = DIN / 2;       // 28 for 57, 8 for 16 (both even)
    u64 w2[NP];
#pragma unroll
    for (int m = 0; m < NP; ++m)
        w2[m] = pk2(sw[r * DPAD + 2 * m], sw[r * DPAD + 2 * m + 1]);
    float wt = (DIN & 1) ? sw[r * DPAD + DIN - 1] : 0.0f;

    const float bias = __ldg(bih + r) + __ldg(bhh + r);
    const int outIdx = ((r & 15) << 2) | (r >> 4);

    for (int p = (tid >> 6); p < PPB; p += 4) {
        const ulonglong2* xq = (const ulonglong2*)&sx[p * XPAD];
        u64 a0 = pk2(bias, 0.0f), a1 = 0ull;
#pragma unroll
        for (int m = 0; m < NP / 2; ++m) {
            ulonglong2 q = xq[m];
            a0 = fma2(q.x, w2[2 * m],     a0);
            a1 = fma2(q.y, w2[2 * m + 1], a1);
        }
        float lo, hi;
        upk2(lo, hi, add2(a0, a1));
        float acc = lo + hi;
        if (DIN & 1)
            acc = fmaf(sx[p * XPAD + DIN - 1], wt, acc);
        xg[((size_t)(posBase + p) << 6) + outIdx] = acc;
    }
}

// ---------------- recurrent scan ------------------------------------------
// 16 lanes per batch, 2 batches/warp, 8 warps/CTA (=> 2 warps per SMSP).
// h broadcast via double-buffered smem: 1 STS + 1 syncwarp + 4 LDS.128,
// quads read as ulonglong2 giving pre-aligned f32x2 pairs.
__global__ void __launch_bounds__(256)
scan_kernel(const float4* __restrict__ xg,
            const float*  __restrict__ Whh,   // [64,16]
            float*        __restrict__ hout,  // [B,T,16]
            const int*    __restrict__ lengths,
            int apply_mask)
{
    __shared__ __align__(16) float sh[8 * 2 * 32];   // [warp][parity][half*16+j]

    const int tid  = threadIdx.x;
    const int wid  = tid >> 5;
    const int lane = tid & 31;
    const int j    = lane & 15;
    const int half = lane >> 4;
    const int b    = blockIdx.x * 16 + (wid << 1) + half;

    // per-unit recurrent weights, k-packed into f32x2 pairs
    u64 wi2[8], wf2[8], wg2[8], wo2[8];
    {
        const float2* ri = (const float2*)(Whh + ( 0 + j) * 16);
        const float2* rf = (const float2*)(Whh + (16 + j) * 16);
        const float2* rg = (const float2*)(Whh + (32 + j) * 16);
        const float2* ro = (const float2*)(Whh + (48 + j) * 16);
#pragma unroll
        for (int m = 0; m < 8; ++m) {
            float2 a = __ldg(ri + m), bb = __ldg(rf + m);
            float2 cc = __ldg(rg + m), dd = __ldg(ro + m);
            wi2[m] = pk2(a.x, a.y);
            wf2[m] = pk2(bb.x, bb.y);
            wg2[m] = pk2(cc.x, cc.y);
            wo2[m] = pk2(dd.x, dd.y);
        }
    }
    const int len = apply_mask ? lengths[b] : TT;

    const float4* xp = xg   + (size_t)b * TT * 16 + j;
    float*        hp = hout + (size_t)b * TT * 16 + j;

    float* shW = sh + wid * 64;            // this warp's 2 parity buffers
    // step t reads parity (t&1)^1, writes parity (t&1); t=0 reads parity 1
    shW[32 + lane] = 0.0f;                 // zero parity-1 buffer (both halves)
    __syncwarp();

    float c = 0.0f;
    float4 buf[8];
#pragma unroll
    for (int u = 0; u < 8; ++u) buf[u] = xp[u * 16];

    for (int tb = 0; tb < TT; tb += 8) {
#pragma unroll
        for (int u = 0; u < 8; ++u) {
            const int t = tb + u;
            const float4 cur = buf[u];
            buf[u] = xp[(t + 8) * 16];       // padded array: safe past the end

            const ulonglong2* q = (const ulonglong2*)(shW + ((u & 1) ^ 1) * 32 + half * 16);
            ulonglong2 q0 = q[0], q1 = q[1];

            u64 ai0 = pk2(cur.x, 0.0f), af0 = pk2(cur.y, 0.0f);
            u64 ag0 = pk2(cur.z, 0.0f), ao0 = pk2(cur.w, 0.0f);
            ai0 = fma2(q0.x, wi2[0], ai0);  af0 = fma2(q0.x, wf2[0], af0);
            ag0 = fma2(q0.x, wg2[0], ag0);  ao0 = fma2(q0.x, wo2[0], ao0);
            ai0 = fma2(q0.y, wi2[1], ai0);  af0 = fma2(q0.y, wf2[1], af0);
            ag0 = fma2(q0.y, wg2[1], ag0);  ao0 = fma2(q0.y, wo2[1], ao0);
            ai0 = fma2(q1.x, wi2[2], ai0);  af0 = fma2(q1.x, wf2[2], af0);
            ag0 = fma2(q1.x, wg2[2], ag0);  ao0 = fma2(q1.x, wo2[2], ao0);
            ai0 = fma2(q1.y, wi2[3], ai0);  af0 = fma2(q1.y, wf2[3], af0);
            ag0 = fma2(q1.y, wg2[3], ag0);  ao0 = fma2(q1.y, wo2[3], ao0);

            ulonglong2 q2 = q[2], q3 = q[3];
            u64 ai1 = fma2(q2.x, wi2[4], 0ull), af1 = fma2(q2.x, wf2[4], 0ull);
            u64 ag1 = fma2(q2.x, wg2[4], 0ull), ao1 = fma2(q2.x, wo2[4], 0ull);
            ai1 = fma2(q2.y, wi2[5], ai1);  af1 = fma2(q2.y, wf2[5], af1);
            ag1 = fma2(q2.y, wg2[5], ag1);  ao1 = fma2(q2.y, wo2[5], ao1);
            ai1 = fma2(q3.x, wi2[6], ai1);  af1 = fma2(q3.x, wf2[6], af1);
            ag1 = fma2(q3.x, wg2[6], ag1);  ao1 = fma2(q3.x, wo2[6], ao1);
            ai1 = fma2(q3.y, wi2[7], ai1);  af1 = fma2(q3.y, wf2[7], af1);
            ag1 = fma2(q3.y, wg2[7], ag1);  ao1 = fma2(q3.y, wo2[7], ao1);

            float l0, h0, l1, h1, l2, h2, l3, h3;
            upk2(l0, h0, add2(ai0, ai1)); float a_i = l0 + h0;
            upk2(l1, h1, add2(af0, af1)); float a_f = l1 + h1;
            upk2(l2, h2, add2(ag0, ag1)); float a_g = l2 + h2;
            upk2(l3, h3, add2(ao0, ao1)); float a_o = l3 + h3;

            float gi = f_sigm(a_i);
            float gf = f_sigm(a_f);
            float gg = f_tanh(a_g);
            float go = f_sigm(a_o);
            c = fmaf(gf, c, gi * gg);
            float hn = go * f_tanh(c);

            shW[(u & 1) * 32 + half * 16 + j] = hn;    // publish for next step
            hp[t * 16] = (t < len) ? hn : 0.0f;
            __syncwarp();
        }
    }
}

// ---------------- BN stats --------------------------------------------------
__global__ void zero_stats_kernel() {
    if (threadIdx.x < 32) g_stats[threadIdx.x] = 0.0f;
}

__global__ void stats_kernel(const float* __restrict__ h2)
{
    __shared__ float ss[16], sq[16];
    int tid = threadIdx.x;
    if (tid < 16) { ss[tid] = 0.0f; sq[tid] = 0.0f; }
    __syncthreads();
    int j = tid & 15;
    int rpb = blockDim.x >> 4;
    float s = 0.0f, s2 = 0.0f;
    for (int pos = blockIdx.x * rpb + (tid >> 4); pos < NPOS; pos += gridDim.x * rpb) {
        float v = h2[(size_t)pos * 16 + j];
        s += v; s2 += v * v;
    }
    atomicAdd(&ss[j], s);
    atomicAdd(&sq[j], s2);
    __syncthreads();
    if (tid < 16) {
        atomicAdd(&g_stats[tid],      ss[tid]);
        atomicAdd(&g_stats[16 + tid], sq[tid]);
    }
}

// ---------------- fold BN into FC ------------------------------------------
__global__ void coef_kernel(const float* __restrict__ gamma,
                            const float* __restrict__ beta,
                            const float* __restrict__ fcw,
                            const float* __restrict__ fcb)
{
    __shared__ float scl[16], sht[16];
    int tid = threadIdx.x;
    if (tid < 16) {
        const float inv_n = 1.0f / (float)NPOS;
        float mean = g_stats[tid] * inv_n;
        float var  = g_stats[16 + tid] * inv_n - mean * mean;
        float s = rsqrtf(var + 1e-5f) * gamma[tid];
        scl[tid] = s;
        sht[tid] = beta[tid] - mean * s;
    }
    __syncthreads();
    if (tid < 64) {
        int o = tid >> 4, jj = tid & 15;
        g_coef[tid] = fcw[o * 16 + jj] * scl[jj];
    }
    if (tid < 4) {
        float bb = fcb[tid];
        for (int jj = 0; jj < 16; ++jj)
            bb += fcw[tid * 16 + jj] * sht[jj];
        g_coef[64 + tid] = bb;
    }
}

// ---------------- final GEMV ------------------------------------------------
__global__ void out_kernel(const float* __restrict__ h2, float* __restrict__ out)
{
    int pos = blockIdx.x * blockDim.x + threadIdx.x;
    if (pos >= NPOS) return;
    const float4* hp = (const float4*)(h2 + (size_t)pos * 16);
    float4 v0 = hp[0], v1 = hp[1], v2 = hp[2], v3 = hp[3];
    float hv[16] = { v0.x, v0.y, v0.z, v0.w, v1.x, v1.y, v1.z, v1.w,
                     v2.x, v2.y, v2.z, v2.w, v3.x, v3.y, v3.z, v3.w };
    float o0 = g_coef[64], o1 = g_coef[65], o2 = g_coef[66], o3 = g_coef[67];
#pragma unroll
    for (int jj = 0; jj < 16; ++jj) {
        float hvv = hv[jj];
        o0 = fmaf(hvv, g_coef[ 0 + jj], o0);
        o1 = fmaf(hvv, g_coef[16 + jj], o1);
        o2 = fmaf(hvv, g_coef[32 + jj], o2);
        o3 = fmaf(hvv, g_coef[48 + jj], o3);
    }
    float4 r = { o0, o1, o2, o3 };
    ((float4*)out)[pos] = r;
}

// ---------------- host ------------------------------------------------------
extern "C" void kernel_launch(void* const* d_in, const int* in_sizes, int n_in,
                              void* d_out, int out_size)
{
    const float* x    = (const float*)d_in[0];
    const int*   len  = (const int*)  d_in[1];
    const float* Wih0 = (const float*)d_in[2];
    const float* Whh0 = (const float*)d_in[3];
    const float* bih0 = (const float*)d_in[4];
    const float* bhh0 = (const float*)d_in[5];
    const float* Wih1 = (const float*)d_in[6];
    const float* Whh1 = (const float*)d_in[7];
    const float* bih1 = (const float*)d_in[8];
    const float* bhh1 = (const float*)d_in[9];
    const float* Wih2 = (const float*)d_in[10];
    const float* Whh2 = (const float*)d_in[11];
    const float* bih2 = (const float*)d_in[12];
    const float* bhh2 = (const float*)d_in[13];
    const float* gam  = (const float*)d_in[14];
    const float* bet  = (const float*)d_in[15];
    const float* fcw  = (const float*)d_in[16];
    const float* fcb  = (const float*)d_in[17];

    float *xg, *ha, *hb;
    cudaGetSymbolAddress((void**)&xg, g_xg);
    cudaGetSymbolAddress((void**)&ha, g_ha);
    cudaGetSymbolAddress((void**)&hb, g_hb);

    constexpr int PPB = 64;
    const int proj_grid = NPOS / PPB;   // 8192

    // layer 0
    proj_kernel<DD0, PPB><<<proj_grid, 256>>>(x, Wih0, bih0, bhh0, xg);
    scan_kernel<<<BB / 16, 256>>>((const float4*)xg, Whh0, ha, len, 0);
    // layer 1
    proj_kernel<HH, PPB><<<proj_grid, 256>>>(ha, Wih1, bih1, bhh1, xg);
    scan_kernel<<<BB / 16, 256>>>((const float4*)xg, Whh1, hb, len, 0);
    // layer 2 (mask applied at store)
    proj_kernel<HH, PPB><<<proj_grid, 256>>>(hb, Wih2, bih2, bhh2, xg);
    scan_kernel<<<BB / 16, 256>>>((const float4*)xg, Whh2, ha, len, 1);

    // BN stats + fold into FC + output
    zero_stats_kernel<<<1, 32>>>();
    stats_kernel<<<1024, 256>>>(ha);
    coef_kernel<<<1, 64>>>(gam, bet, fcw, fcb);
    out_kernel<<<NPOS / 256, 256>>>(ha, (float*)d_out);
}